// round 1
// baseline (speedup 1.0000x reference)
#include <cuda_runtime.h>

#define BATCH  8
#define NPTS   100000
#define NCLS   10
#define KTOP   1000
#define NROWS  (BATCH * NCLS)      // 80
#define NFLAT  (NCLS * KTOP)       // 10000
#define NW     16                  // 16 x u64 words cover 1024 >= KTOP bits
#define SORTN2 16384
#define ORD_NEG1 0x407FFFFFu       // f2ord(-1.0f)
#define TI     512

// ---------------- static device scratch (no runtime allocation) -------------
__device__ unsigned int       d_ord[NROWS * NPTS];       // 32 MB, per-row ordered score bits
__device__ unsigned long long d_k1 [NROWS * KTOP];       // stage-1 sorted top-1000 keys per row
__device__ unsigned long long d_k2 [BATCH * NFLAT];      // stage-2 candidate keys per batch

// ---------------- helpers ----------------------------------------------------
__device__ __forceinline__ unsigned int f2ord(float f) {
    unsigned int b = __float_as_uint(f);
    return b ^ ((b & 0x80000000u) ? 0xFFFFFFFFu : 0x80000000u);
}
__device__ __forceinline__ float ord2f(unsigned int u) {
    unsigned int b = u ^ ((u & 0x80000000u) ? 0x80000000u : 0xFFFFFFFFu);
    return __uint_as_float(b);
}

// Generic in-shared-memory bitonic sort, descending, n = power of two.
__device__ void bitonic_desc(unsigned long long* s, int n) {
    for (int k = 2; k <= n; k <<= 1) {
        for (int j = k >> 1; j > 0; j >>= 1) {
            __syncthreads();
            for (int i = threadIdx.x; i < n; i += blockDim.x) {
                int ixj = i ^ j;
                if (ixj > i) {
                    unsigned long long a = s[i], bb = s[ixj];
                    if ((a < bb) == ((i & k) == 0)) { s[i] = bb; s[ixj] = a; }
                }
            }
        }
    }
    __syncthreads();
}

// Suppression bitmask: smask[i*NW + w] bit (j - w*64) set iff j > i and IoU > thresh.
// Corners stored as float4 = (y1, x1, y2, x2).
__device__ void build_mask(const float4* scor, unsigned long long* smask, float thresh) {
    for (int t = threadIdx.x; t < KTOP * NW; t += blockDim.x) {
        int i = t / NW;
        int w = t % NW;
        unsigned long long m = 0ULL;
        int jbase = w << 6;
        int j0 = max(jbase, i + 1);
        int j1 = min(jbase + 64, KTOP);
        if (j0 < j1) {
            float4 a = scor[i];
            float areaA = (a.z - a.x) * (a.w - a.y);
            for (int j = j0; j < j1; ++j) {
                float4 c = scor[j];
                float ih = fmaxf(fminf(a.z, c.z) - fmaxf(a.x, c.x), 0.0f);
                float iw = fmaxf(fminf(a.w, c.w) - fmaxf(a.y, c.y), 0.0f);
                float inter = ih * iw;
                float areaB = (c.z - c.x) * (c.w - c.y);
                float iou = inter / fmaxf(areaA + areaB - inter, 1e-8f);
                if (iou > thresh) m |= 1ULL << (j - jbase);
            }
        }
        smask[t] = m;
    }
}

// Sequential greedy scan, warp 0. skeep[i] = valid[i] && !suppressed-at-i.
__device__ void nms_scan(const unsigned char* svalid, const unsigned long long* smask,
                         unsigned char* skeep) {
    if (threadIdx.x < 32) {
        int lane = threadIdx.x;
        unsigned long long rem = 0ULL;          // lanes 0..15 own removed word [lane]
        for (int i = 0; i < KTOP; ++i) {
            unsigned long long rw = __shfl_sync(0xFFFFFFFFu, rem, i >> 6);
            bool alive = svalid[i] && !((rw >> (i & 63)) & 1ULL);
            if (alive && lane < NW) rem |= smask[i * NW + lane];
            if (lane == 0) skeep[i] = alive ? 1 : 0;
        }
    }
    __syncthreads();
}

// ---------------- kernel 1: mask + transpose scores to per-(b,c) rows --------
__global__ void k_transpose(const float* __restrict__ cls) {
    __shared__ unsigned int tile[TI * NCLS];
    int b  = blockIdx.y;
    int i0 = blockIdx.x * TI;
    int cnt = min(TI, NPTS - i0);
    const float* src = cls + ((size_t)b * NPTS + i0) * NCLS;
    for (int t = threadIdx.x; t < cnt * NCLS; t += blockDim.x) {
        float s = src[t];
        s = (s >= 0.05f) ? s : -1.0f;
        tile[t] = f2ord(s);
    }
    __syncthreads();
    for (int c = 0; c < NCLS; ++c) {
        unsigned int* dst = d_ord + (size_t)(b * NCLS + c) * NPTS + i0;
        for (int r = threadIdx.x; r < cnt; r += blockDim.x)
            dst[r] = tile[r * NCLS + c];
    }
}

// ---------------- kernel 2: per-(b,c) radix select + sort + NMS(0.4) ---------
// smem layout (dynamic):
//   hist   u32[256]          @ 0       (1024 B)
//   sbig   u64[1024]         @ 1024    (8192 B)
//   stie   u64[256]          @ 9216    (2048 B)
//   sfin   u64[1024]         @ 11264   (8192 B)
//   scor   float4[1024]      @ 19456   (16384 B)
//   svalid u8[1024]          @ 35840
//   skeep  u8[1024]          @ 36864
//   smask  u64[KTOP*NW]      @ 37888   (128000 B)   total = 165888
#define SMEM1 165888

__global__ void __launch_bounds__(1024, 1) k_stage1(const float4* __restrict__ boxes) {
    extern __shared__ char sm[];
    unsigned int*       hist   = (unsigned int*)sm;
    unsigned long long* sbig   = (unsigned long long*)(sm + 1024);
    unsigned long long* stie   = (unsigned long long*)(sm + 9216);
    unsigned long long* sfin   = (unsigned long long*)(sm + 11264);
    float4*             scor   = (float4*)(sm + 19456);
    unsigned char*      svalid = (unsigned char*)(sm + 35840);
    unsigned char*      skeep  = (unsigned char*)(sm + 36864);
    unsigned long long* smask  = (unsigned long long*)(sm + 37888);
    __shared__ unsigned int sprefix;
    __shared__ int skrem, sng, snt;

    int row = blockIdx.x;
    int b = row / NCLS, c = row % NCLS;
    const unsigned int* ord = d_ord + (size_t)row * NPTS;
    int tid = threadIdx.x, bd = blockDim.x;
    int lane = tid & 31;

    if (tid == 0) { sprefix = 0u; skrem = KTOP; }

    // ---- 4-pass 8-bit radix select for the exact 1000th-largest score bits
    const int nIter = (NPTS + 1024 - 1) / 1024;
    for (int p = 0; p < 4; ++p) {
        int shift = 24 - 8 * p;
        for (int t = tid; t < 256; t += bd) hist[t] = 0u;
        __syncthreads();
        unsigned int pref = sprefix;
        for (int it = 0; it < nIter; ++it) {
            int i = it * bd + tid;
            bool inr = (i < NPTS);
            unsigned int u = inr ? ord[i] : 0u;
            bool part = inr;
            if (p != 0) part = part && ((u >> (shift + 8)) == pref);
            unsigned int dgt = (u >> shift) & 255u;
            unsigned int act = __ballot_sync(0xFFFFFFFFu, part);
            if (part) {   // warp-aggregate same-digit atomics (digits concentrate heavily)
                unsigned int peers = __match_any_sync(act, dgt);
                if (lane == (__ffs(peers) - 1))
                    atomicAdd(&hist[dgt], (unsigned int)__popc(peers));
            }
        }
        __syncthreads();
        if (tid == 0) {
            int cum = 0, sel = 0, krem = skrem;
            for (int dd = 255; dd >= 0; --dd) {
                int h = (int)hist[dd];
                if (cum + h >= krem) { sel = dd; break; }
                cum += h;
            }
            skrem = krem - cum;
            sprefix = (sprefix << 8) | (unsigned int)sel;
        }
        __syncthreads();
    }
    unsigned int T = sprefix;
    int krem = skrem;                 // how many == T to take (smallest indices)
    if (tid == 0) { sng = 0; snt = 0; }
    __syncthreads();

    // ---- collect strictly-greater + tie candidates
    for (int i = tid; i < NPTS; i += bd) {
        unsigned int u = ord[i];
        if (u > T) {
            int p = atomicAdd(&sng, 1);
            if (p < 1024) sbig[p] = ((unsigned long long)u << 32) | (unsigned int)(~i);
        } else if (u == T) {
            int p = atomicAdd(&snt, 1);
            if (p < 256) stie[p] = ((unsigned long long)u << 32) | (unsigned int)(~i);
        }
    }
    __syncthreads();
    int ng  = min(sng, 1024);
    int ntt = min(snt, 256);
    for (int t = tid; t < 256; t += bd) if (t >= ntt) stie[t] = 0ULL;
    bitonic_desc(stie, 256);          // equal score -> ascending index (matches lax.top_k)
    int take = min(krem, ntt);
    for (int t = tid; t < 1024; t += bd) {
        unsigned long long v = 0ULL;
        if (t < ng) v = sbig[t];
        else if (t < ng + take) v = stie[t - ng];
        sfin[t] = v;
    }
    bitonic_desc(sfin, 1024);         // full descending order for greedy NMS

    // ---- decode, gather boxes, corners
    for (int k = tid; k < KTOP; k += bd) {
        unsigned long long key = sfin[k];
        d_k1[row * KTOP + k] = key;
        unsigned int hi = (unsigned int)(key >> 32);
        float s = ord2f(hi);
        bool valid = (s >= 0.05f);
        unsigned int idx = ~(unsigned int)key;
        if (!valid || idx >= NPTS) idx = 0;   // pad safety; invalid boxes never suppress
        float4 bb = boxes[(size_t)b * NPTS + idx];  // (cx, cy, w, h)
        scor[k] = make_float4(bb.y - 0.5f * bb.w, bb.x - 0.5f * bb.z,
                              bb.y + 0.5f * bb.w, bb.x + 0.5f * bb.z);
        svalid[k] = valid ? 1 : 0;
    }
    __syncthreads();

    build_mask(scor, smask, 0.4f);
    __syncthreads();
    nms_scan(svalid, smask, skeep);

    // ---- emit stage-2 keys: kept -> (score, ~flat); else (-1, ~flat)
    for (int k = tid; k < KTOP; k += bd) {
        unsigned int hi = skeep[k] ? (unsigned int)(sfin[k] >> 32) : ORD_NEG1;
        unsigned int flat = (unsigned int)(c * KTOP + k);
        d_k2[b * NFLAT + flat] = ((unsigned long long)hi << 32) | (unsigned int)(~flat);
    }
}

// ---------------- kernel 3: per-batch sort + NMS(0.65) + compaction ----------
// smem layout (dynamic):
//   sarr u64[16384] @ 0       (131072 B)  sort area, reused as mask (needs 128000 B)
//   kbuf u64[1024]  @ 131072  (8192 B)
//   scor float4[1024] @ 139264 (16384 B)
//   svalid/skeep u8[1024] @ 155648 / 156672
//   spos int[1024] @ 157696  (4096 B)     total = 161792
#define SMEM2 161792

__global__ void __launch_bounds__(1024, 1) k_stage2(const float4* __restrict__ boxes,
                                                    float* __restrict__ out) {
    extern __shared__ char sm[];
    unsigned long long* sarr   = (unsigned long long*)sm;
    unsigned long long* kbuf   = (unsigned long long*)(sm + 131072);
    float4*             scor   = (float4*)(sm + 139264);
    unsigned char*      svalid = (unsigned char*)(sm + 155648);
    unsigned char*      skeep  = (unsigned char*)(sm + 156672);
    int*                spos   = (int*)(sm + 157696);

    int b = blockIdx.x;
    int tid = threadIdx.x, bd = blockDim.x;

    for (int t = tid; t < SORTN2; t += bd)
        sarr[t] = (t < NFLAT) ? d_k2[b * NFLAT + t] : 0ULL;
    bitonic_desc(sarr, SORTN2);               // exact lax.top_k order of s2
    for (int t = tid; t < 1024; t += bd) kbuf[t] = sarr[t];
    __syncthreads();

    float4 myraw = make_float4(0.f, 0.f, 0.f, 0.f);
    float myconf = 0.f;
    int mycls = 0;
    if (tid < KTOP) {
        unsigned long long key = kbuf[tid];
        unsigned int hi = (unsigned int)(key >> 32);
        float s = ord2f(hi);
        bool valid = (s >= 0.05f);            // v2; NaN pads fail this too
        unsigned int flat = ~(unsigned int)key;
        unsigned int orig = 0;
        int cc = 0;
        if (valid && flat < NFLAT) {
            cc = (int)(flat / KTOP);
            unsigned int kk = flat % KTOP;
            orig = ~(unsigned int)d_k1[(b * NCLS + cc) * KTOP + kk];
            if (orig >= NPTS) orig = 0;
        } else {
            valid = false;
        }
        float4 bb = boxes[(size_t)b * NPTS + orig];
        myraw = bb; myconf = s; mycls = cc;
        scor[tid] = make_float4(bb.y - 0.5f * bb.w, bb.x - 0.5f * bb.z,
                                bb.y + 0.5f * bb.w, bb.x + 0.5f * bb.z);
        svalid[tid] = valid ? 1 : 0;
    }
    __syncthreads();

    build_mask(scor, sarr, 0.65f);            // reuse sort area as mask
    __syncthreads();
    nms_scan(svalid, sarr, skeep);

    // stable compaction = jnp.argsort(!keep) semantics
    int flag = (tid < KTOP && skeep[tid]) ? 1 : 0;
    spos[tid] = flag;
    __syncthreads();
    for (int off = 1; off < 1024; off <<= 1) {
        int v = spos[tid];
        if (tid >= off) v += spos[tid - off];
        __syncthreads();
        spos[tid] = v;
        __syncthreads();
    }
    int total = spos[1023];
    if (flag) {
        int m = spos[tid] - 1;
        float* o = out + ((size_t)b * KTOP + m) * 6;
        o[0] = myraw.x; o[1] = myraw.y; o[2] = myraw.z; o[3] = myraw.w;
        o[4] = (float)mycls; o[5] = myconf;
    }
    for (int m = total + tid; m < KTOP; m += bd) {
        float* o = out + ((size_t)b * KTOP + m) * 6;
        #pragma unroll
        for (int q = 0; q < 6; ++q) o[q] = 0.f;
    }
}

// ---------------- launch ------------------------------------------------------
extern "C" void kernel_launch(void* const* d_in, const int* in_sizes, int n_in,
                              void* d_out, int out_size) {
    const float*  cls   = (const float*)d_in[0];   // (8, 100000, 10)
    const float4* boxes = (const float4*)d_in[1];  // (8, 100000, 4)
    float* out = (float*)d_out;                    // (8, 1000, 6)

    cudaFuncSetAttribute(k_stage1, cudaFuncAttributeMaxDynamicSharedMemorySize, SMEM1);
    cudaFuncSetAttribute(k_stage2, cudaFuncAttributeMaxDynamicSharedMemorySize, SMEM2);

    dim3 gT((NPTS + TI - 1) / TI, BATCH);
    k_transpose<<<gT, 512>>>(cls);
    k_stage1<<<NROWS, 1024, SMEM1>>>(boxes);
    k_stage2<<<BATCH, 1024, SMEM2>>>(boxes, out);
}

// round 5
// speedup vs baseline: 1.7007x; 1.7007x over previous
#include <cuda_runtime.h>

typedef unsigned int u32;
typedef unsigned long long u64;

#define BATCH  8
#define NPTS   100000
#define NCLS   10
#define KTOP   1000
#define NROWS  (BATCH * NCLS)      // 80
#define NFLAT  (NCLS * KTOP)       // 10000
#define NW     16                  // u64 words covering 1024 bits
#define NPAD   1024                // padded row count for the scan (16 blocks x 64)
#define ORD_NEG1 0x407FFFFFu       // f2ord(-1.0f)
#define TI     512
#define SCAN_SMEM (NPAD * NW * 8)  // 131072 bytes

// ---------------- static device scratch -------------------------------------
__device__ u32    d_ord  [NROWS * NPTS];        // 32 MB ordered score bits
__device__ u64    d_k1   [NROWS * KTOP];        // stage-1 sorted keys
__device__ u64    d_val1 [NROWS * NW];
__device__ float4 d_corn1[NROWS * KTOP];
__device__ u64    d_mask1[NROWS * KTOP * NW];   // 10.24 MB
__device__ u64    d_k2   [BATCH * NFLAT];
__device__ u64    d_k2s  [BATCH * KTOP];
__device__ u64    d_val2 [BATCH * NW];
__device__ float4 d_corn2[BATCH * KTOP];
__device__ float4 d_raw2 [BATCH * KTOP];
__device__ u64    d_mask2[BATCH * KTOP * NW];

// ---------------- helpers ----------------------------------------------------
__device__ __forceinline__ u32 f2ord(float f) {
    u32 b = __float_as_uint(f);
    return b ^ ((b & 0x80000000u) ? 0xFFFFFFFFu : 0x80000000u);
}
__device__ __forceinline__ float ord2f(u32 u) {
    u32 b = u ^ ((u & 0x80000000u) ? 0x80000000u : 0xFFFFFFFFu);
    return __uint_as_float(b);
}

__device__ void bitonic_desc(u64* s, int n) {
    for (int k = 2; k <= n; k <<= 1) {
        for (int j = k >> 1; j > 0; j >>= 1) {
            __syncthreads();
            for (int i = threadIdx.x; i < n; i += blockDim.x) {
                int ixj = i ^ j;
                if (ixj > i) {
                    u64 a = s[i], bb = s[ixj];
                    if ((a < bb) == ((i & k) == 0)) { s[i] = bb; s[ixj] = a; }
                }
            }
        }
    }
    __syncthreads();
}

// Warp-aggregated histogram add. MUST be called by fully-converged warps:
// all 32 lanes execute, non-participants pass part=false.
__device__ __forceinline__ void hist_add(u32* hist, bool part, u32 dgt, int lane) {
    u32 act = __ballot_sync(0xFFFFFFFFu, part);
    if (part) {
        u32 peers = __match_any_sync(act, dgt);
        if (lane == __ffs(peers) - 1)
            atomicAdd(&hist[dgt], (u32)__popc(peers));
    }
}

// Find highest 12-bit bin so that count(> bin) < K <= count(>= bin).
// hist[4096], sscan[1024], exactly 1024 threads. Result -> *s_sel, *s_krem.
__device__ void select_bin(u32* hist, u32* sscan, int K, u32* s_sel, int* s_krem) {
    int t = threadIdx.x;
    u32 h0 = hist[4 * t], h1 = hist[4 * t + 1], h2 = hist[4 * t + 2], h3 = hist[4 * t + 3];
    u32 mysum = h0 + h1 + h2 + h3;
    sscan[t] = mysum;
    __syncthreads();
    u32 v = mysum;
    for (int off = 1; off < 1024; off <<= 1) {
        u32 add = (t + off < 1024) ? sscan[t + off] : 0u;
        __syncthreads();
        v += add;
        sscan[t] = v;
        __syncthreads();
    }
    u32 above = (t < 1023) ? sscan[t + 1] : 0u;   // suffix sum over higher threads
    if (above < (u32)K && above + mysum >= (u32)K) {
        u32 cum = above;
        u32 hh[4] = { h3, h2, h1, h0 };
        int bb[4] = { 4 * t + 3, 4 * t + 2, 4 * t + 1, 4 * t };
        #pragma unroll
        for (int q = 0; q < 4; q++) {
            if (cum + hh[q] >= (u32)K) { *s_sel = (u32)bb[q]; *s_krem = K - (int)cum; break; }
            cum += hh[q];
        }
    }
    __syncthreads();
}

// Blocked greedy NMS scan by warp 0.  smask in SMEM, NPAD(=1024) rows x NW words
// (rows >= KTOP are zero / never-valid padding).  V = per-lane valid word
// (lanes 0..15), keep words -> skw[16].
__device__ void warp_scan(const u64* smask, u64 V, u64* skw) {
    int lane = threadIdx.x & 31;
    u64 rem = 0ULL;
    for (int blk = 0; blk < 16; blk++) {
        u64 Sb = __shfl_sync(0xFFFFFFFFu, rem, blk);
        u64 Vb = __shfl_sync(0xFFFFFFFFu, V, blk);
        int base = blk << 6;
        u64 aliveM = 0ULL;
        if (lane == 0) {
            for (int q0 = 0; q0 < 64; q0 += 8) {
                u64 dw[8];
                #pragma unroll
                for (int r = 0; r < 8; r++) dw[r] = smask[(base + q0 + r) * NW + blk];
                #pragma unroll
                for (int r = 0; r < 8; r++) {
                    int q = q0 + r;
                    if (((Vb >> q) & 1ULL) && !((Sb >> q) & 1ULL)) {
                        Sb |= dw[r];
                        aliveM |= 1ULL << q;
                    }
                }
            }
            skw[blk] = aliveM;
        }
        aliveM = __shfl_sync(0xFFFFFFFFu, aliveM, 0);
        int lw = lane & 15;
        #pragma unroll 8
        for (int q = 0; q < 64; q++) {
            u64 sel = (u64)0 - ((aliveM >> q) & 1ULL);
            rem |= smask[(base + q) * NW + lw] & sel;
        }
    }
}

// ---------------- K1: mask + transpose to per-(b,c) rows --------------------
__global__ void k_transpose(const float* __restrict__ cls) {
    __shared__ u32 tile[TI * NCLS];
    int b  = blockIdx.y;
    int i0 = blockIdx.x * TI;
    int cnt = min(TI, NPTS - i0);
    const float* src = cls + ((size_t)b * NPTS + i0) * NCLS;
    for (int t = threadIdx.x; t < cnt * NCLS; t += blockDim.x) {
        float s = src[t];
        s = (s >= 0.05f) ? s : -1.0f;
        tile[t] = f2ord(s);
    }
    __syncthreads();
    for (int c = 0; c < NCLS; ++c) {
        u32* dst = d_ord + (size_t)(b * NCLS + c) * NPTS + i0;
        for (int r = threadIdx.x; r < cnt; r += blockDim.x)
            dst[r] = tile[r * NCLS + c];
    }
}

// ---------------- K2: stage-1 select (2x12-bit radix) + sort -----------------
__global__ void __launch_bounds__(1024) k_sel1(const float4* __restrict__ boxes) {
    __shared__ u32 hist[4096];
    __shared__ u32 sscan[1024];
    __shared__ u64 sbig[1024], stie[256], sfin[1024];
    __shared__ u64 sval[16];
    __shared__ u32 s_sel;
    __shared__ int s_krem, s_ng, s_nt;

    int row = blockIdx.x;
    int b = row / NCLS, c = row % NCLS;
    const u32* ord = d_ord + (size_t)row * NPTS;
    int tid = threadIdx.x, lane = tid & 31;
    const int nIter = (NPTS + 1023) / 1024;

    if (tid == 0) { s_ng = 0; s_nt = 0; }
    if (tid < 16) sval[tid] = 0ULL;
    for (int t = tid; t < 4096; t += 1024) hist[t] = 0u;
    __syncthreads();

    // pass A: digit = bits 31..20  (uniform trip count; guard folded into part)
    for (int it = 0; it < nIter; it++) {
        int i = it * 1024 + tid;
        bool inr = (i < NPTS);
        u32 u = inr ? ord[i] : 0u;
        hist_add(hist, inr, u >> 20, lane);
    }
    __syncthreads();
    select_bin(hist, sscan, KTOP, &s_sel, &s_krem);
    u32 D1 = s_sel;
    int K2v = s_krem;

    // pass B: digit = bits 19..8 among prefix matches
    for (int t = tid; t < 4096; t += 1024) hist[t] = 0u;
    __syncthreads();
    for (int it = 0; it < nIter; it++) {
        int i = it * 1024 + tid;
        bool inr = (i < NPTS);
        u32 u = inr ? ord[i] : 0u;
        bool part = inr && ((u >> 20) == D1);
        hist_add(hist, part, (u >> 8) & 4095u, lane);
    }
    __syncthreads();
    select_bin(hist, sscan, K2v, &s_sel, &s_krem);
    u32 T24 = (D1 << 12) | s_sel;
    int krem = s_krem;

    // collect: > prefix and == prefix (ties); no warp collectives inside
    for (int i = tid; i < NPTS; i += 1024) {
        u32 u = ord[i];
        u32 p24 = u >> 8;
        if (p24 > T24) {
            int pos = atomicAdd(&s_ng, 1);
            if (pos < 1024) sbig[pos] = ((u64)u << 32) | (u32)(~i);
        } else if (p24 == T24) {
            int pos = atomicAdd(&s_nt, 1);
            if (pos < 256) stie[pos] = ((u64)u << 32) | (u32)(~i);
        }
    }
    __syncthreads();
    int ng = min(s_ng, 1024), nt = min(s_nt, 256);
    int take = min(krem, nt);
    for (int t = tid; t < 256; t += 1024) if (t >= nt) stie[t] = 0ULL;
    bitonic_desc(stie, 256);
    for (int t = tid; t < 1024; t += 1024) {
        u64 v = 0ULL;
        if (t < ng) v = sbig[t];
        else if (t < ng + take) v = stie[t - ng];
        sfin[t] = v;
    }
    bitonic_desc(sfin, 1024);

    if (tid < KTOP) {
        u64 key = sfin[tid];
        d_k1[row * KTOP + tid] = key;
        u32 hi = (u32)(key >> 32);
        float s = ord2f(hi);
        bool valid = (s >= 0.05f);
        u32 idx = ~(u32)key;
        if (!valid || idx >= NPTS) idx = 0;
        float4 bb = boxes[(size_t)b * NPTS + idx];
        d_corn1[row * KTOP + tid] = make_float4(bb.y - 0.5f * bb.w, bb.x - 0.5f * bb.z,
                                                bb.y + 0.5f * bb.w, bb.x + 0.5f * bb.z);
        if (valid) atomicOr(&sval[tid >> 6], 1ULL << (tid & 63));
    }
    __syncthreads();
    if (tid < 16) d_val1[row * NW + tid] = sval[tid];
}

// ---------------- K3/K6: full-chip mask build --------------------------------
__device__ __forceinline__ void mask_body(const float4* corn, u64* mg, float thresh) {
    __shared__ float4 scor[KTOP];
    int row = blockIdx.y;
    const float4* cr = corn + (size_t)row * KTOP;
    for (int t = threadIdx.x; t < KTOP; t += blockDim.x) scor[t] = cr[t];
    __syncthreads();
    int chunk = (KTOP * NW) / gridDim.x;
    int t0 = blockIdx.x * chunk;
    for (int t = t0 + threadIdx.x; t < t0 + chunk; t += blockDim.x) {
        int i = t >> 4, w = t & 15;
        u64 m = 0ULL;
        int jbase = w << 6;
        int j0 = max(jbase, i + 1);
        int j1 = min(jbase + 64, KTOP);
        if (j0 < j1) {
            float4 a = scor[i];
            float areaA = (a.z - a.x) * (a.w - a.y);
            for (int j = j0; j < j1; ++j) {
                float4 cc = scor[j];
                float ih = fmaxf(fminf(a.z, cc.z) - fmaxf(a.x, cc.x), 0.0f);
                float iw = fmaxf(fminf(a.w, cc.w) - fmaxf(a.y, cc.y), 0.0f);
                float inter = ih * iw;
                float areaB = (cc.z - cc.x) * (cc.w - cc.y);
                float iou = inter / fmaxf(areaA + areaB - inter, 1e-8f);
                if (iou > thresh) m |= 1ULL << (j - jbase);
            }
        }
        mg[(size_t)row * KTOP * NW + t] = m;
    }
}
__global__ void __launch_bounds__(256) k_mask1() { mask_body(d_corn1, d_mask1, 0.4f); }
__global__ void __launch_bounds__(256) k_mask2() { mask_body(d_corn2, d_mask2, 0.65f); }

// ---------------- K4: stage-1 NMS scan + stage-2 key emission ----------------
__global__ void __launch_bounds__(128) k_scan1() {
    extern __shared__ u64 smS[];
    u64* smask = smS;                    // NPAD*NW words (padded)
    __shared__ u64 skw[16];
    int row = blockIdx.x, tid = threadIdx.x;
    int b = row / NCLS, c = row % NCLS;
    const u64* mg = d_mask1 + (size_t)row * KTOP * NW;
    for (int t = tid; t < KTOP * NW; t += 128) smask[t] = mg[t];
    for (int t = KTOP * NW + tid; t < NPAD * NW; t += 128) smask[t] = 0ULL;
    __syncthreads();
    if (tid < 32) {
        u64 V = (tid < 16) ? d_val1[row * NW + tid] : 0ULL;
        warp_scan(smask, V, skw);
    }
    __syncthreads();
    for (int k = tid; k < KTOP; k += 128) {
        bool kept = (skw[k >> 6] >> (k & 63)) & 1ULL;
        u32 hi = kept ? (u32)(d_k1[row * KTOP + k] >> 32) : ORD_NEG1;
        u32 flat = (u32)(c * KTOP + k);
        d_k2[b * NFLAT + flat] = ((u64)hi << 32) | (u32)(~flat);
    }
}

// ---------------- K5: stage-2 radix select + sort + gather -------------------
__global__ void __launch_bounds__(1024) k_sel2(const float4* __restrict__ boxes) {
    extern __shared__ u64 skeys[];       // NFLAT
    __shared__ u32 hist[4096];
    __shared__ u32 sscan[1024];
    __shared__ u64 sbig[1024], stie[256], sfin[1024];
    __shared__ u64 sval[16];
    __shared__ u32 s_sel;
    __shared__ int s_krem, s_ng, s_nt;

    int b = blockIdx.x, tid = threadIdx.x, lane = tid & 31;
    for (int f = tid; f < NFLAT; f += 1024) skeys[f] = d_k2[b * NFLAT + f];
    if (tid == 0) { s_ng = 0; s_nt = 0; }
    if (tid < 16) sval[tid] = 0ULL;
    __syncthreads();

    const int nIt2 = (NFLAT + 1023) / 1024;   // uniform trip count for collectives
    u64 prefix = 0ULL;
    int Kc = KTOP;
    for (int p = 0; p < 5; p++) {
        int shift = 52 - 12 * p;
        for (int t = tid; t < 4096; t += 1024) hist[t] = 0u;
        __syncthreads();
        for (int it = 0; it < nIt2; it++) {
            int f = it * 1024 + tid;
            bool inr = (f < NFLAT);
            u64 k = inr ? skeys[f] : 0ULL;
            bool part = inr && ((p == 0) || ((k >> (shift + 12)) == prefix));
            hist_add(hist, part, (u32)((k >> shift) & 4095ULL), lane);
        }
        __syncthreads();
        select_bin(hist, sscan, Kc, &s_sel, &s_krem);
        prefix = (prefix << 12) | (u64)s_sel;
        Kc = s_krem;
    }

    for (int f = tid; f < NFLAT; f += 1024) {   // no collectives inside
        u64 k = skeys[f];
        u64 p60 = k >> 4;
        if (p60 > prefix) {
            int pos = atomicAdd(&s_ng, 1);
            if (pos < 1024) sbig[pos] = k;
        } else if (p60 == prefix) {
            int pos = atomicAdd(&s_nt, 1);
            if (pos < 256) stie[pos] = k;
        }
    }
    __syncthreads();
    int ng = min(s_ng, 1024), nt = min(s_nt, 256);
    int take = min(Kc, nt);
    for (int t = tid; t < 256; t += 1024) if (t >= nt) stie[t] = 0ULL;
    bitonic_desc(stie, 256);
    for (int t = tid; t < 1024; t += 1024) {
        u64 v = 0ULL;
        if (t < ng) v = sbig[t];
        else if (t < ng + take) v = stie[t - ng];
        sfin[t] = v;
    }
    bitonic_desc(sfin, 1024);

    if (tid < KTOP) {
        u64 key = sfin[tid];
        d_k2s[b * KTOP + tid] = key;
        u32 hi = (u32)(key >> 32);
        float s = ord2f(hi);
        bool valid = (s >= 0.05f);
        u32 flat = ~(u32)key;
        u32 orig = 0;
        int cc2 = 0;
        if (valid && flat < NFLAT) {
            cc2 = (int)(flat / KTOP);
            u32 kk = flat % KTOP;
            orig = ~(u32)d_k1[(b * NCLS + cc2) * KTOP + kk];
            if (orig >= NPTS) orig = 0;
        } else valid = false;
        float4 bb = boxes[(size_t)b * NPTS + orig];
        d_raw2[b * KTOP + tid] = bb;
        d_corn2[b * KTOP + tid] = make_float4(bb.y - 0.5f * bb.w, bb.x - 0.5f * bb.z,
                                              bb.y + 0.5f * bb.w, bb.x + 0.5f * bb.z);
        if (valid) atomicOr(&sval[tid >> 6], 1ULL << (tid & 63));
    }
    __syncthreads();
    if (tid < 16) d_val2[b * NW + tid] = sval[tid];
}

// ---------------- K7: stage-2 NMS scan + compaction + output -----------------
__global__ void __launch_bounds__(1024) k_out(float* __restrict__ out) {
    extern __shared__ u64 smS[];
    u64* smask = smS;                    // NPAD*NW words (padded)
    __shared__ u64 skw[16];
    __shared__ int spos[1024];
    int b = blockIdx.x, tid = threadIdx.x;
    const u64* mg = d_mask2 + (size_t)b * KTOP * NW;
    for (int t = tid; t < KTOP * NW; t += 1024) smask[t] = mg[t];
    for (int t = KTOP * NW + tid; t < NPAD * NW; t += 1024) smask[t] = 0ULL;
    __syncthreads();
    if (tid < 32) {
        u64 V = (tid < 16) ? d_val2[b * NW + tid] : 0ULL;
        warp_scan(smask, V, skw);
    }
    __syncthreads();

    bool kept = false;
    float conf = 0.0f;
    int cls = 0;
    float4 raw = make_float4(0.f, 0.f, 0.f, 0.f);
    if (tid < KTOP) {
        kept = (skw[tid >> 6] >> (tid & 63)) & 1ULL;
        if (kept) {
            u64 key = d_k2s[b * KTOP + tid];
            conf = ord2f((u32)(key >> 32));
            u32 flat = ~(u32)key;
            cls = (int)(flat / KTOP);
            raw = d_raw2[b * KTOP + tid];
        }
    }
    int flag = kept ? 1 : 0;
    spos[tid] = flag;
    __syncthreads();
    for (int off = 1; off < 1024; off <<= 1) {
        int v = spos[tid];
        int add = (tid >= off) ? spos[tid - off] : 0;
        __syncthreads();
        spos[tid] = v + add;
        __syncthreads();
    }
    int total = spos[1023];
    if (flag) {
        int m = spos[tid] - 1;
        float* o = out + ((size_t)b * KTOP + m) * 6;
        o[0] = raw.x; o[1] = raw.y; o[2] = raw.z; o[3] = raw.w;
        o[4] = (float)cls; o[5] = conf;
    }
    for (int m = total + tid; m < KTOP; m += 1024) {
        float* o = out + ((size_t)b * KTOP + m) * 6;
        #pragma unroll
        for (int q = 0; q < 6; ++q) o[q] = 0.f;
    }
}

// ---------------- launch ------------------------------------------------------
extern "C" void kernel_launch(void* const* d_in, const int* in_sizes, int n_in,
                              void* d_out, int out_size) {
    const float*  cls   = (const float*)d_in[0];
    const float4* boxes = (const float4*)d_in[1];
    float* out = (float*)d_out;

    cudaFuncSetAttribute(k_scan1, cudaFuncAttributeMaxDynamicSharedMemorySize, SCAN_SMEM);
    cudaFuncSetAttribute(k_sel2,  cudaFuncAttributeMaxDynamicSharedMemorySize, NFLAT * 8);
    cudaFuncSetAttribute(k_out,   cudaFuncAttributeMaxDynamicSharedMemorySize, SCAN_SMEM);

    k_transpose<<<dim3((NPTS + TI - 1) / TI, BATCH), 512>>>(cls);
    k_sel1<<<NROWS, 1024>>>(boxes);
    k_mask1<<<dim3(8, NROWS), 256>>>();
    k_scan1<<<NROWS, 128, SCAN_SMEM>>>();
    k_sel2<<<BATCH, 1024, NFLAT * 8>>>(boxes);
    k_mask2<<<dim3(8, BATCH), 256>>>();
    k_out<<<BATCH, 1024, SCAN_SMEM>>>(out);
}

// round 6
// speedup vs baseline: 1.8231x; 1.0720x over previous
#include <cuda_runtime.h>

typedef unsigned int u32;
typedef unsigned long long u64;

#define BATCH  8
#define NPTS   100000
#define NCLS   10
#define KTOP   1000
#define NROWS  (BATCH * NCLS)      // 80
#define NFLAT  (NCLS * KTOP)       // 10000
#define NW     16                  // u64 words covering 1024 bits
#define ORD_NEG1 0x407FFFFFu       // f2ord(-1.0f)
#define TI     512

// ---------------- static device scratch -------------------------------------
__device__ u32    d_ord  [NROWS * NPTS];        // 32 MB ordered score bits
__device__ u64    d_k1   [NROWS * KTOP];        // stage-1 sorted keys
__device__ u64    d_val1 [NROWS * NW];
__device__ float4 d_corn1[NROWS * KTOP];
__device__ u64    d_k2   [BATCH * NFLAT];
__device__ u64    d_k2s  [BATCH * KTOP];
__device__ u64    d_val2 [BATCH * NW];
__device__ float4 d_corn2[BATCH * KTOP];
__device__ float4 d_raw2 [BATCH * KTOP];

// ---------------- helpers ----------------------------------------------------
__device__ __forceinline__ u32 f2ord(float f) {
    u32 b = __float_as_uint(f);
    return b ^ ((b & 0x80000000u) ? 0xFFFFFFFFu : 0x80000000u);
}
__device__ __forceinline__ float ord2f(u32 u) {
    u32 b = u ^ ((u & 0x80000000u) ? 0x80000000u : 0xFFFFFFFFu);
    return __uint_as_float(b);
}

__device__ __forceinline__ bool iou_gt(float4 a, float areaA, float4 c, float thresh) {
    float ih = fmaxf(fminf(a.z, c.z) - fmaxf(a.x, c.x), 0.0f);
    float iw = fmaxf(fminf(a.w, c.w) - fmaxf(a.y, c.y), 0.0f);
    float inter = ih * iw;
    float areaB = (c.z - c.x) * (c.w - c.y);
    float iou = inter / fmaxf(areaA + areaB - inter, 1e-8f);
    return iou > thresh;
}

__device__ void bitonic_desc(u64* s, int n) {
    for (int k = 2; k <= n; k <<= 1) {
        for (int j = k >> 1; j > 0; j >>= 1) {
            __syncthreads();
            for (int i = threadIdx.x; i < n; i += blockDim.x) {
                int ixj = i ^ j;
                if (ixj > i) {
                    u64 a = s[i], bb = s[ixj];
                    if ((a < bb) == ((i & k) == 0)) { s[i] = bb; s[ixj] = a; }
                }
            }
        }
    }
    __syncthreads();
}

// Warp-aggregated histogram add. MUST be called by fully-converged warps.
__device__ __forceinline__ void hist_add(u32* hist, bool part, u32 dgt, int lane) {
    u32 act = __ballot_sync(0xFFFFFFFFu, part);
    if (part) {
        u32 peers = __match_any_sync(act, dgt);
        if (lane == __ffs(peers) - 1)
            atomicAdd(&hist[dgt], (u32)__popc(peers));
    }
}

// Highest 12-bit bin with count(> bin) < K <= count(>= bin). 1024 threads.
__device__ void select_bin(u32* hist, u32* sscan, int K, u32* s_sel, int* s_krem) {
    int t = threadIdx.x;
    u32 h0 = hist[4 * t], h1 = hist[4 * t + 1], h2 = hist[4 * t + 2], h3 = hist[4 * t + 3];
    u32 mysum = h0 + h1 + h2 + h3;
    sscan[t] = mysum;
    __syncthreads();
    u32 v = mysum;
    for (int off = 1; off < 1024; off <<= 1) {
        u32 add = (t + off < 1024) ? sscan[t + off] : 0u;
        __syncthreads();
        v += add;
        sscan[t] = v;
        __syncthreads();
    }
    u32 above = (t < 1023) ? sscan[t + 1] : 0u;
    if (above < (u32)K && above + mysum >= (u32)K) {
        u32 cum = above;
        u32 hh[4] = { h3, h2, h1, h0 };
        int bb[4] = { 4 * t + 3, 4 * t + 2, 4 * t + 1, 4 * t };
        #pragma unroll
        for (int q = 0; q < 4; q++) {
            if (cum + hh[q] >= (u32)K) { *s_sel = (u32)bb[q]; *s_krem = K - (int)cum; break; }
            cum += hh[q];
        }
    }
    __syncthreads();
}

// ---------------- lazy blocked greedy NMS (in-smem, 1024 threads) ------------
// scor: KTOP corners (y1,x1,y2,x2). val/rem/keep: 16 u64 words. Exactly
// equivalent to the sequential greedy recurrence: only boxes alive when the
// scan reaches them suppress later boxes.
struct NmsShared {
    u64 val[NW];
    u64 rem[NW];
    u64 keep[NW];
    u64 mat[64];
    int aliveList[64];
    int aliveCnt;
};

__device__ void lazy_nms(const float4* scor, NmsShared* ns, float thresh, int tid) {
    for (int blk = 0; blk < NW; blk++) {
        int base = blk << 6;
        // cand is uniform: all threads read identical smem after the previous sync
        u64 cand = ns->val[blk] & ~ns->rem[blk];
        if (tid < 64) ns->mat[tid] = 0ULL;
        __syncthreads();

        // phase A: intra-block 64x64 pairs for candidate i's (4 pairs/thread)
        {
            int i = tid >> 4;
            if ((cand >> i) & 1ULL) {
                int gi = base + i;
                float4 a = scor[gi];
                float areaA = (a.z - a.x) * (a.w - a.y);
                int j0 = (tid & 15) * 4;
                u64 bits = 0ULL;
                #pragma unroll
                for (int q = 0; q < 4; q++) {
                    int j = j0 + q;
                    int gj = base + j;
                    if (j > i && gj < KTOP) {
                        if (iou_gt(a, areaA, scor[gj], thresh)) bits |= 1ULL << j;
                    }
                }
                if (bits) atomicOr(&ns->mat[i], bits);
            }
        }
        __syncthreads();

        // serial resolve of this block (thread 0)
        if (tid == 0) {
            u64 suppB = ns->rem[blk];
            u64 vB = ns->val[blk];
            u64 aliveB = 0ULL;
            for (int q = 0; q < 64; q++) {
                if (((vB >> q) & 1ULL) && !((suppB >> q) & 1ULL)) {
                    aliveB |= 1ULL << q;
                    suppB |= ns->mat[q];
                }
            }
            ns->keep[blk] = aliveB;
            int n = 0;
            u64 tmp = aliveB;
            while (tmp) {
                int q = __ffsll(tmp) - 1;
                ns->aliveList[n++] = base + q;
                tmp &= tmp - 1;
            }
            ns->aliveCnt = n;
        }
        __syncthreads();

        // phase B: alive boxes of this block suppress all later boxes
        {
            int nA = ns->aliveCnt;
            int jstart = base + 64;
            int nLater = KTOP - jstart;
            if (nLater > 0) {
                int tot = nA * nLater;
                for (int x = tid; x < tot; x += 1024) {
                    int ii = ns->aliveList[x / nLater];
                    int j  = jstart + x % nLater;
                    float4 a = scor[ii];
                    float areaA = (a.z - a.x) * (a.w - a.y);
                    if (iou_gt(a, areaA, scor[j], thresh))
                        atomicOr(&ns->rem[j >> 6], 1ULL << (j & 63));
                }
            }
        }
        __syncthreads();
    }
}

// ---------------- K1: mask + transpose to per-(b,c) rows --------------------
__global__ void k_transpose(const float* __restrict__ cls) {
    __shared__ u32 tile[TI * NCLS];
    int b  = blockIdx.y;
    int i0 = blockIdx.x * TI;
    int cnt = min(TI, NPTS - i0);
    const float* src = cls + ((size_t)b * NPTS + i0) * NCLS;
    for (int t = threadIdx.x; t < cnt * NCLS; t += blockDim.x) {
        float s = src[t];
        s = (s >= 0.05f) ? s : -1.0f;
        tile[t] = f2ord(s);
    }
    __syncthreads();
    for (int c = 0; c < NCLS; ++c) {
        u32* dst = d_ord + (size_t)(b * NCLS + c) * NPTS + i0;
        for (int r = threadIdx.x; r < cnt; r += blockDim.x)
            dst[r] = tile[r * NCLS + c];
    }
}

// ---------------- K2: stage-1 select (2x12-bit radix) + sort -----------------
__global__ void __launch_bounds__(1024) k_sel1(const float4* __restrict__ boxes) {
    __shared__ u32 hist[4096];
    __shared__ u32 sscan[1024];
    __shared__ u64 sbig[1024], stie[256], sfin[1024];
    __shared__ u64 sval[16];
    __shared__ u32 s_sel;
    __shared__ int s_krem, s_ng, s_nt;

    int row = blockIdx.x;
    int b = row / NCLS, c = row % NCLS;
    const u32* ord = d_ord + (size_t)row * NPTS;
    int tid = threadIdx.x, lane = tid & 31;
    const int nIter = (NPTS + 1023) / 1024;

    if (tid == 0) { s_ng = 0; s_nt = 0; }
    if (tid < 16) sval[tid] = 0ULL;
    for (int t = tid; t < 4096; t += 1024) hist[t] = 0u;
    __syncthreads();

    for (int it = 0; it < nIter; it++) {
        int i = it * 1024 + tid;
        bool inr = (i < NPTS);
        u32 u = inr ? ord[i] : 0u;
        hist_add(hist, inr, u >> 20, lane);
    }
    __syncthreads();
    select_bin(hist, sscan, KTOP, &s_sel, &s_krem);
    u32 D1 = s_sel;
    int K2v = s_krem;

    for (int t = tid; t < 4096; t += 1024) hist[t] = 0u;
    __syncthreads();
    for (int it = 0; it < nIter; it++) {
        int i = it * 1024 + tid;
        bool inr = (i < NPTS);
        u32 u = inr ? ord[i] : 0u;
        bool part = inr && ((u >> 20) == D1);
        hist_add(hist, part, (u >> 8) & 4095u, lane);
    }
    __syncthreads();
    select_bin(hist, sscan, K2v, &s_sel, &s_krem);
    u32 T24 = (D1 << 12) | s_sel;
    int krem = s_krem;

    for (int i = tid; i < NPTS; i += 1024) {
        u32 u = ord[i];
        u32 p24 = u >> 8;
        if (p24 > T24) {
            int pos = atomicAdd(&s_ng, 1);
            if (pos < 1024) sbig[pos] = ((u64)u << 32) | (u32)(~i);
        } else if (p24 == T24) {
            int pos = atomicAdd(&s_nt, 1);
            if (pos < 256) stie[pos] = ((u64)u << 32) | (u32)(~i);
        }
    }
    __syncthreads();
    int ng = min(s_ng, 1024), nt = min(s_nt, 256);
    int take = min(krem, nt);
    for (int t = tid; t < 256; t += 1024) if (t >= nt) stie[t] = 0ULL;
    bitonic_desc(stie, 256);
    for (int t = tid; t < 1024; t += 1024) {
        u64 v = 0ULL;
        if (t < ng) v = sbig[t];
        else if (t < ng + take) v = stie[t - ng];
        sfin[t] = v;
    }
    bitonic_desc(sfin, 1024);

    if (tid < KTOP) {
        u64 key = sfin[tid];
        d_k1[row * KTOP + tid] = key;
        u32 hi = (u32)(key >> 32);
        float s = ord2f(hi);
        bool valid = (s >= 0.05f);
        u32 idx = ~(u32)key;
        if (!valid || idx >= NPTS) idx = 0;
        float4 bb = boxes[(size_t)b * NPTS + idx];
        d_corn1[row * KTOP + tid] = make_float4(bb.y - 0.5f * bb.w, bb.x - 0.5f * bb.z,
                                                bb.y + 0.5f * bb.w, bb.x + 0.5f * bb.z);
        if (valid) atomicOr(&sval[tid >> 6], 1ULL << (tid & 63));
    }
    __syncthreads();
    if (tid < 16) d_val1[row * NW + tid] = sval[tid];
}

// ---------------- K3: fused lazy NMS (stage 1) + stage-2 key emission --------
__global__ void __launch_bounds__(1024) k_nms1() {
    __shared__ float4 scor[KTOP];
    __shared__ NmsShared ns;
    int row = blockIdx.x, tid = threadIdx.x;
    int b = row / NCLS, c = row % NCLS;

    for (int k = tid; k < KTOP; k += 1024) scor[k] = d_corn1[(size_t)row * KTOP + k];
    if (tid < NW) {
        ns.val[tid] = d_val1[row * NW + tid];
        ns.rem[tid] = 0ULL;
        ns.keep[tid] = 0ULL;
    }
    __syncthreads();

    lazy_nms(scor, &ns, 0.4f, tid);

    for (int k = tid; k < KTOP; k += 1024) {
        bool kept = (ns.keep[k >> 6] >> (k & 63)) & 1ULL;
        u32 hi = kept ? (u32)(d_k1[row * KTOP + k] >> 32) : ORD_NEG1;
        u32 flat = (u32)(c * KTOP + k);
        d_k2[b * NFLAT + flat] = ((u64)hi << 32) | (u32)(~flat);
    }
}

// ---------------- K4: stage-2 radix select + sort + gather -------------------
__global__ void __launch_bounds__(1024) k_sel2(const float4* __restrict__ boxes) {
    extern __shared__ u64 skeys[];       // NFLAT
    __shared__ u32 hist[4096];
    __shared__ u32 sscan[1024];
    __shared__ u64 sbig[1024], stie[256], sfin[1024];
    __shared__ u64 sval[16];
    __shared__ u32 s_sel;
    __shared__ int s_krem, s_ng, s_nt;

    int b = blockIdx.x, tid = threadIdx.x, lane = tid & 31;
    for (int f = tid; f < NFLAT; f += 1024) skeys[f] = d_k2[b * NFLAT + f];
    if (tid == 0) { s_ng = 0; s_nt = 0; }
    if (tid < 16) sval[tid] = 0ULL;
    __syncthreads();

    const int nIt2 = (NFLAT + 1023) / 1024;
    u64 prefix = 0ULL;
    int Kc = KTOP;
    for (int p = 0; p < 5; p++) {
        int shift = 52 - 12 * p;
        for (int t = tid; t < 4096; t += 1024) hist[t] = 0u;
        __syncthreads();
        for (int it = 0; it < nIt2; it++) {
            int f = it * 1024 + tid;
            bool inr = (f < NFLAT);
            u64 k = inr ? skeys[f] : 0ULL;
            bool part = inr && ((p == 0) || ((k >> (shift + 12)) == prefix));
            hist_add(hist, part, (u32)((k >> shift) & 4095ULL), lane);
        }
        __syncthreads();
        select_bin(hist, sscan, Kc, &s_sel, &s_krem);
        prefix = (prefix << 12) | (u64)s_sel;
        Kc = s_krem;
    }

    for (int f = tid; f < NFLAT; f += 1024) {
        u64 k = skeys[f];
        u64 p60 = k >> 4;
        if (p60 > prefix) {
            int pos = atomicAdd(&s_ng, 1);
            if (pos < 1024) sbig[pos] = k;
        } else if (p60 == prefix) {
            int pos = atomicAdd(&s_nt, 1);
            if (pos < 256) stie[pos] = k;
        }
    }
    __syncthreads();
    int ng = min(s_ng, 1024), nt = min(s_nt, 256);
    int take = min(Kc, nt);
    for (int t = tid; t < 256; t += 1024) if (t >= nt) stie[t] = 0ULL;
    bitonic_desc(stie, 256);
    for (int t = tid; t < 1024; t += 1024) {
        u64 v = 0ULL;
        if (t < ng) v = sbig[t];
        else if (t < ng + take) v = stie[t - ng];
        sfin[t] = v;
    }
    bitonic_desc(sfin, 1024);

    if (tid < KTOP) {
        u64 key = sfin[tid];
        d_k2s[b * KTOP + tid] = key;
        u32 hi = (u32)(key >> 32);
        float s = ord2f(hi);
        bool valid = (s >= 0.05f);
        u32 flat = ~(u32)key;
        u32 orig = 0;
        int cc2 = 0;
        if (valid && flat < NFLAT) {
            cc2 = (int)(flat / KTOP);
            u32 kk = flat % KTOP;
            orig = ~(u32)d_k1[(b * NCLS + cc2) * KTOP + kk];
            if (orig >= NPTS) orig = 0;
        } else valid = false;
        float4 bb = boxes[(size_t)b * NPTS + orig];
        d_raw2[b * KTOP + tid] = bb;
        d_corn2[b * KTOP + tid] = make_float4(bb.y - 0.5f * bb.w, bb.x - 0.5f * bb.z,
                                              bb.y + 0.5f * bb.w, bb.x + 0.5f * bb.z);
        if (valid) atomicOr(&sval[tid >> 6], 1ULL << (tid & 63));
    }
    __syncthreads();
    if (tid < 16) d_val2[b * NW + tid] = sval[tid];
}

// ---------------- K5: fused lazy NMS (stage 2) + compaction + output ---------
__global__ void __launch_bounds__(1024) k_nms2(float* __restrict__ out) {
    __shared__ float4 scor[KTOP];
    __shared__ NmsShared ns;
    __shared__ int spos[1024];
    int b = blockIdx.x, tid = threadIdx.x;

    for (int k = tid; k < KTOP; k += 1024) scor[k] = d_corn2[(size_t)b * KTOP + k];
    if (tid < NW) {
        ns.val[tid] = d_val2[b * NW + tid];
        ns.rem[tid] = 0ULL;
        ns.keep[tid] = 0ULL;
    }
    __syncthreads();

    lazy_nms(scor, &ns, 0.65f, tid);

    bool kept = false;
    float conf = 0.0f;
    int cls = 0;
    float4 raw = make_float4(0.f, 0.f, 0.f, 0.f);
    if (tid < KTOP) {
        kept = (ns.keep[tid >> 6] >> (tid & 63)) & 1ULL;
        if (kept) {
            u64 key = d_k2s[b * KTOP + tid];
            conf = ord2f((u32)(key >> 32));
            u32 flat = ~(u32)key;
            cls = (int)(flat / KTOP);
            raw = d_raw2[b * KTOP + tid];
        }
    }
    int flag = kept ? 1 : 0;
    spos[tid] = flag;
    __syncthreads();
    for (int off = 1; off < 1024; off <<= 1) {
        int v = spos[tid];
        int add = (tid >= off) ? spos[tid - off] : 0;
        __syncthreads();
        spos[tid] = v + add;
        __syncthreads();
    }
    int total = spos[1023];
    if (flag) {
        int m = spos[tid] - 1;
        float* o = out + ((size_t)b * KTOP + m) * 6;
        o[0] = raw.x; o[1] = raw.y; o[2] = raw.z; o[3] = raw.w;
        o[4] = (float)cls; o[5] = conf;
    }
    for (int m = total + tid; m < KTOP; m += 1024) {
        float* o = out + ((size_t)b * KTOP + m) * 6;
        #pragma unroll
        for (int q = 0; q < 6; ++q) o[q] = 0.f;
    }
}

// ---------------- launch ------------------------------------------------------
extern "C" void kernel_launch(void* const* d_in, const int* in_sizes, int n_in,
                              void* d_out, int out_size) {
    const float*  cls   = (const float*)d_in[0];
    const float4* boxes = (const float4*)d_in[1];
    float* out = (float*)d_out;

    cudaFuncSetAttribute(k_sel2, cudaFuncAttributeMaxDynamicSharedMemorySize, NFLAT * 8);

    k_transpose<<<dim3((NPTS + TI - 1) / TI, BATCH), 512>>>(cls);
    k_sel1<<<NROWS, 1024>>>(boxes);
    k_nms1<<<NROWS, 1024>>>();
    k_sel2<<<BATCH, 1024, NFLAT * 8>>>(boxes);
    k_nms2<<<BATCH, 1024>>>(out);
}

// round 7
// speedup vs baseline: 1.9447x; 1.0667x over previous
#include <cuda_runtime.h>

typedef unsigned int u32;
typedef unsigned long long u64;

#define BATCH  8
#define NPTS   100000
#define NCLS   10
#define KTOP   1000
#define NROWS  (BATCH * NCLS)      // 80
#define NFLAT  (NCLS * KTOP)       // 10000
#define ORD_NEG1 0x407FFFFFu       // f2ord(-1.0f)
#define TI     512

// ---------------- static device scratch -------------------------------------
__device__ u32    d_ord  [NROWS * NPTS];        // 32 MB ordered score bits
__device__ u64    d_k1   [NROWS * KTOP];        // stage-1 sorted keys
__device__ float4 d_corn1[NROWS * KTOP];
__device__ u64    d_k2   [BATCH * NFLAT];
__device__ u64    d_k2s  [BATCH * KTOP];
__device__ float4 d_corn2[BATCH * KTOP];
__device__ float4 d_raw2 [BATCH * KTOP];

// ---------------- helpers ----------------------------------------------------
__device__ __forceinline__ u32 f2ord(float f) {
    u32 b = __float_as_uint(f);
    return b ^ ((b & 0x80000000u) ? 0xFFFFFFFFu : 0x80000000u);
}
__device__ __forceinline__ float ord2f(u32 u) {
    u32 b = u ^ ((u & 0x80000000u) ? 0x80000000u : 0xFFFFFFFFu);
    return __uint_as_float(b);
}

__device__ void bitonic_desc(u64* s, int n) {
    for (int k = 2; k <= n; k <<= 1) {
        for (int j = k >> 1; j > 0; j >>= 1) {
            __syncthreads();
            for (int i = threadIdx.x; i < n; i += blockDim.x) {
                int ixj = i ^ j;
                if (ixj > i) {
                    u64 a = s[i], bb = s[ixj];
                    if ((a < bb) == ((i & k) == 0)) { s[i] = bb; s[ixj] = a; }
                }
            }
        }
    }
    __syncthreads();
}

// Warp-aggregated histogram add. Call with fully-converged warps only.
__device__ __forceinline__ void hist_add(u32* hist, bool part, u32 dgt, int lane) {
    u32 act = __ballot_sync(0xFFFFFFFFu, part);
    if (part) {
        u32 peers = __match_any_sync(act, dgt);
        if (lane == __ffs(peers) - 1)
            atomicAdd(&hist[dgt], (u32)__popc(peers));
    }
}

// Highest 12-bit bin with count(> bin) < K <= count(>= bin).  1024 threads.
// Suffix sums via warp shuffles: 3 barriers total.
__device__ void select_bin(const u32* hist, u32* swarp, int K, u32* s_sel, int* s_krem) {
    int t = threadIdx.x, lane = t & 31, wid = t >> 5;
    u32 h0 = hist[4 * t], h1 = hist[4 * t + 1], h2 = hist[4 * t + 2], h3 = hist[4 * t + 3];
    u32 mysum = h0 + h1 + h2 + h3;
    u32 v = mysum;                        // in-warp inclusive suffix sum
    #pragma unroll
    for (int off = 1; off < 32; off <<= 1) {
        u32 n = __shfl_down_sync(0xFFFFFFFFu, v, off);
        if (lane + off < 32) v += n;
    }
    if (lane == 0) swarp[wid] = v;        // warp total
    __syncthreads();
    if (t < 32) {
        u32 w = swarp[t];
        #pragma unroll
        for (int off = 1; off < 32; off <<= 1) {
            u32 n = __shfl_down_sync(0xFFFFFFFFu, w, off);
            if (lane + off < 32) w += n;
        }
        swarp[t] = w;                     // suffix-incl over warp totals
    }
    __syncthreads();
    u32 S_incl = v + ((wid < 31) ? swarp[wid + 1] : 0u);
    u32 above = S_incl - mysum;           // count in threads strictly above t
    if (above < (u32)K && S_incl >= (u32)K) {
        u32 cum = above;
        u32 hh[4] = { h3, h2, h1, h0 };
        int bb[4] = { 4 * t + 3, 4 * t + 2, 4 * t + 1, 4 * t };
        #pragma unroll
        for (int q = 0; q < 4; q++) {
            if (cum + hh[q] >= (u32)K) { *s_sel = (u32)bb[q]; *s_krem = K - (int)cum; break; }
            cum += hh[q];
        }
    }
    __syncthreads();
}

// ---------------- thread-owns-box blocked greedy NMS -------------------------
struct NmsSh {
    float4 box[1024];
    float  area[1024];
    u64    mat[64];
    u32    cand[2];
    u64    alive;
};

// 1024 threads; thread tid owns box tid (pads >= KTOP have myvalid=false).
// Exactly the sequential greedy recurrence: only boxes alive when the scan
// reaches them suppress later boxes. Returns kept for this thread's box.
__device__ bool nms_greedy(NmsSh* ns, float4 my, float myarea, bool myvalid,
                           float thresh, int tid) {
    bool supp = false, kept = false;
    int myblk = tid >> 6;
    int lane = tid & 31;
    for (int blk = 0; blk < 16; blk++) {
        // step 1: block blk publishes candidacy (valid && not yet suppressed)
        if ((tid >> 6) == blk) {                 // warp-uniform (2 warps)
            u32 bal = __ballot_sync(0xFFFFFFFFu, myvalid && !supp);
            if (lane == 0) ns->cand[(tid >> 5) & 1] = bal;
        }
        __syncthreads();
        u64 cand = ((u64)ns->cand[1] << 32) | (u64)ns->cand[0];
        int base = blk << 6;

        // step 2: intra-block 64x64 matrix (4 j's per thread, shfl-OR reduce)
        {
            int i = tid >> 4;
            u64 bits = 0ULL;
            if ((cand >> i) & 1ULL) {
                float4 a = ns->box[base + i];
                float areaA = ns->area[base + i];
                int j0 = (tid & 15) << 2;
                #pragma unroll
                for (int q = 0; q < 4; q++) {
                    int j = j0 + q;
                    if (j > i) {
                        float4 c = ns->box[base + j];
                        float ih = fmaxf(fminf(a.z, c.z) - fmaxf(a.x, c.x), 0.0f);
                        float iw = fmaxf(fminf(a.w, c.w) - fmaxf(a.y, c.y), 0.0f);
                        float inter = ih * iw;
                        float uni = fmaxf(areaA + ns->area[base + j] - inter, 1e-8f);
                        if (inter / uni > thresh) bits |= 1ULL << j;
                    }
                }
            }
            #pragma unroll
            for (int off = 8; off; off >>= 1)
                bits |= __shfl_xor_sync(0xFFFFFFFFu, bits, off);
            if ((tid & 15) == 0) ns->mat[tid >> 4] = bits;
        }
        __syncthreads();

        // step 3: serial resolve (thread 0, 8-wide prefetch)
        if (tid == 0) {
            u64 suppB = 0ULL, aliveB = 0ULL;
            for (int q0 = 0; q0 < 64; q0 += 8) {
                u64 dw[8];
                #pragma unroll
                for (int r = 0; r < 8; r++) dw[r] = ns->mat[q0 + r];
                #pragma unroll
                for (int r = 0; r < 8; r++) {
                    int q = q0 + r;
                    if (((cand >> q) & 1ULL) && !((suppB >> q) & 1ULL)) {
                        aliveB |= 1ULL << q;
                        suppB |= dw[r];
                    }
                }
            }
            ns->alive = aliveB;
        }
        __syncthreads();
        u64 aliveM = ns->alive;

        // step 4: finalize this block; later threads check vs alive boxes
        if (myblk == blk) {
            kept = myvalid && ((aliveM >> (tid & 63)) & 1ULL);
            supp = !kept;
        } else if (myblk > blk && myvalid && !supp) {
            u64 tmp = aliveM;
            while (tmp) {
                int ii = __ffsll(tmp) - 1;
                tmp &= tmp - 1;
                float4 a = ns->box[base + ii];         // broadcast LDS
                float areaA = ns->area[base + ii];
                float ih = fmaxf(fminf(a.z, my.z) - fmaxf(a.x, my.x), 0.0f);
                float iw = fmaxf(fminf(a.w, my.w) - fmaxf(a.y, my.y), 0.0f);
                float inter = ih * iw;
                float uni = fmaxf(areaA + myarea - inter, 1e-8f);
                if (inter / uni > thresh) { supp = true; break; }
            }
        }
        // next loop-top sync orders step-4 reads vs next writes
    }
    return kept;
}

// ---------------- K1: mask + transpose to per-(b,c) rows --------------------
__global__ void k_transpose(const float* __restrict__ cls) {
    __shared__ u32 tile[TI * NCLS];
    int b  = blockIdx.y;
    int i0 = blockIdx.x * TI;
    int cnt = min(TI, NPTS - i0);
    const float* src = cls + ((size_t)b * NPTS + i0) * NCLS;
    for (int t = threadIdx.x; t < cnt * NCLS; t += blockDim.x) {
        float s = src[t];
        s = (s >= 0.05f) ? s : -1.0f;
        tile[t] = f2ord(s);
    }
    __syncthreads();
    for (int c = 0; c < NCLS; ++c) {
        u32* dst = d_ord + (size_t)(b * NCLS + c) * NPTS + i0;
        for (int r = threadIdx.x; r < cnt; r += blockDim.x)
            dst[r] = tile[r * NCLS + c];
    }
}

// ---------------- K2: stage-1 select (2x12-bit radix) + sort -----------------
__global__ void __launch_bounds__(1024) k_sel1(const float4* __restrict__ boxes) {
    __shared__ u32 hist[4096];
    __shared__ u32 swarp[32];
    __shared__ u64 sbig[1024], stie[256], sfin[1024];
    __shared__ u32 s_sel;
    __shared__ int s_krem, s_ng, s_nt;

    int row = blockIdx.x;
    int b = row / NCLS, c = row % NCLS;
    const u32* ord = d_ord + (size_t)row * NPTS;
    int tid = threadIdx.x, lane = tid & 31;
    const int nIter = (NPTS + 1023) / 1024;

    if (tid == 0) { s_ng = 0; s_nt = 0; }
    for (int t = tid; t < 4096; t += 1024) hist[t] = 0u;
    __syncthreads();

    for (int it = 0; it < nIter; it++) {
        int i = it * 1024 + tid;
        bool inr = (i < NPTS);
        u32 u = inr ? ord[i] : 0u;
        hist_add(hist, inr, u >> 20, lane);
    }
    __syncthreads();
    select_bin(hist, swarp, KTOP, &s_sel, &s_krem);
    u32 D1 = s_sel;
    int K2v = s_krem;

    for (int t = tid; t < 4096; t += 1024) hist[t] = 0u;
    __syncthreads();
    for (int it = 0; it < nIter; it++) {
        int i = it * 1024 + tid;
        bool inr = (i < NPTS);
        u32 u = inr ? ord[i] : 0u;
        bool part = inr && ((u >> 20) == D1);
        hist_add(hist, part, (u >> 8) & 4095u, lane);
    }
    __syncthreads();
    select_bin(hist, swarp, K2v, &s_sel, &s_krem);
    u32 T24 = (D1 << 12) | s_sel;
    int krem = s_krem;

    for (int i = tid; i < NPTS; i += 1024) {
        u32 u = ord[i];
        u32 p24 = u >> 8;
        if (p24 > T24) {
            int pos = atomicAdd(&s_ng, 1);
            if (pos < 1024) sbig[pos] = ((u64)u << 32) | (u32)(~i);
        } else if (p24 == T24) {
            int pos = atomicAdd(&s_nt, 1);
            if (pos < 256) stie[pos] = ((u64)u << 32) | (u32)(~i);
        }
    }
    __syncthreads();
    int ng = min(s_ng, 1024), nt = min(s_nt, 256);
    int take = min(krem, nt);
    for (int t = tid; t < 256; t += 1024) if (t >= nt) stie[t] = 0ULL;
    bitonic_desc(stie, 256);
    for (int t = tid; t < 1024; t += 1024) {
        u64 v = 0ULL;
        if (t < ng) v = sbig[t];
        else if (t < ng + take) v = stie[t - ng];
        sfin[t] = v;
    }
    bitonic_desc(sfin, 1024);

    if (tid < KTOP) {
        u64 key = sfin[tid];
        d_k1[row * KTOP + tid] = key;
        u32 hi = (u32)(key >> 32);
        float s = ord2f(hi);
        bool valid = (s >= 0.05f);
        u32 idx = ~(u32)key;
        if (!valid || idx >= NPTS) idx = 0;
        float4 bb = boxes[(size_t)b * NPTS + idx];
        d_corn1[row * KTOP + tid] = make_float4(bb.y - 0.5f * bb.w, bb.x - 0.5f * bb.z,
                                                bb.y + 0.5f * bb.w, bb.x + 0.5f * bb.z);
    }
}

// ---------------- K3: stage-1 NMS + stage-2 key emission ---------------------
__global__ void __launch_bounds__(1024) k_nms1() {
    __shared__ NmsSh ns;
    int row = blockIdx.x, tid = threadIdx.x;
    int b = row / NCLS, c = row % NCLS;
    u64 mykey = 0ULL;
    bool myvalid = false;
    float4 my = make_float4(0.f, 0.f, 0.f, 0.f);
    if (tid < KTOP) {
        mykey = d_k1[row * KTOP + tid];
        myvalid = ord2f((u32)(mykey >> 32)) >= 0.05f;
        my = d_corn1[(size_t)row * KTOP + tid];
    }
    float myarea = (my.z - my.x) * (my.w - my.y);
    ns.box[tid] = my;
    ns.area[tid] = myarea;
    __syncthreads();

    bool kept = nms_greedy(&ns, my, myarea, myvalid, 0.4f, tid);

    if (tid < KTOP) {
        u32 hi = kept ? (u32)(mykey >> 32) : ORD_NEG1;
        u32 flat = (u32)(c * KTOP + tid);
        d_k2[b * NFLAT + flat] = ((u64)hi << 32) | (u32)(~flat);
    }
}

// ---------------- K4: stage-2 select (5x12-bit radix on u64) + gather --------
__global__ void __launch_bounds__(1024) k_sel2(const float4* __restrict__ boxes) {
    __shared__ u32 hist[4096];
    __shared__ u32 swarp[32];
    __shared__ u64 sbig[1024], stie[256], sfin[1024];
    __shared__ u32 s_sel;
    __shared__ int s_krem, s_ng, s_nt;

    int b = blockIdx.x, tid = threadIdx.x, lane = tid & 31;
    const u64* keys = d_k2 + b * NFLAT;
    if (tid == 0) { s_ng = 0; s_nt = 0; }

    const int nIt2 = (NFLAT + 1023) / 1024;
    u64 prefix = 0ULL;
    int Kc = KTOP;
    for (int p = 0; p < 5; p++) {
        int shift = 52 - 12 * p;
        for (int t = tid; t < 4096; t += 1024) hist[t] = 0u;
        __syncthreads();
        for (int it = 0; it < nIt2; it++) {
            int f = it * 1024 + tid;
            bool inr = (f < NFLAT);
            u64 k = inr ? keys[f] : 0ULL;
            bool part = inr && ((p == 0) || ((k >> (shift + 12)) == prefix));
            hist_add(hist, part, (u32)((k >> shift) & 4095ULL), lane);
        }
        __syncthreads();
        select_bin(hist, swarp, Kc, &s_sel, &s_krem);
        prefix = (prefix << 12) | (u64)s_sel;
        Kc = s_krem;
    }

    for (int f = tid; f < NFLAT; f += 1024) {
        u64 k = keys[f];
        u64 p60 = k >> 4;
        if (p60 > prefix) {
            int pos = atomicAdd(&s_ng, 1);
            if (pos < 1024) sbig[pos] = k;
        } else if (p60 == prefix) {
            int pos = atomicAdd(&s_nt, 1);
            if (pos < 256) stie[pos] = k;
        }
    }
    __syncthreads();
    int ng = min(s_ng, 1024), nt = min(s_nt, 256);
    int take = min(Kc, nt);
    for (int t = tid; t < 256; t += 1024) if (t >= nt) stie[t] = 0ULL;
    bitonic_desc(stie, 256);
    for (int t = tid; t < 1024; t += 1024) {
        u64 v = 0ULL;
        if (t < ng) v = sbig[t];
        else if (t < ng + take) v = stie[t - ng];
        sfin[t] = v;
    }
    bitonic_desc(sfin, 1024);

    if (tid < KTOP) {
        u64 key = sfin[tid];
        d_k2s[b * KTOP + tid] = key;
        u32 hi = (u32)(key >> 32);
        float s = ord2f(hi);
        bool valid = (s >= 0.05f);
        u32 flat = ~(u32)key;
        u32 orig = 0;
        if (valid && flat < NFLAT) {
            int cc2 = (int)(flat / KTOP);
            u32 kk = flat % KTOP;
            orig = ~(u32)d_k1[(b * NCLS + cc2) * KTOP + kk];
            if (orig >= NPTS) orig = 0;
        } else valid = false;
        float4 bb = boxes[(size_t)b * NPTS + orig];
        d_raw2[b * KTOP + tid] = bb;
        d_corn2[b * KTOP + tid] = make_float4(bb.y - 0.5f * bb.w, bb.x - 0.5f * bb.z,
                                              bb.y + 0.5f * bb.w, bb.x + 0.5f * bb.z);
    }
}

// ---------------- K5: stage-2 NMS + compaction + output ----------------------
__global__ void __launch_bounds__(1024) k_nms2(float* __restrict__ out) {
    __shared__ NmsSh ns;
    __shared__ int swarp2[32];
    int b = blockIdx.x, tid = threadIdx.x;
    int lane = tid & 31, wid = tid >> 5;

    u64 mykey = 0ULL;
    bool myvalid = false;
    float4 my = make_float4(0.f, 0.f, 0.f, 0.f);
    if (tid < KTOP) {
        mykey = d_k2s[b * KTOP + tid];
        myvalid = ord2f((u32)(mykey >> 32)) >= 0.05f;
        my = d_corn2[(size_t)b * KTOP + tid];
    }
    float myarea = (my.z - my.x) * (my.w - my.y);
    ns.box[tid] = my;
    ns.area[tid] = myarea;
    __syncthreads();

    bool kept = nms_greedy(&ns, my, myarea, myvalid, 0.65f, tid);

    // stable compaction (= argsort(!keep)) via 2-barrier warp scan
    int flag = kept ? 1 : 0;
    int v = flag;
    #pragma unroll
    for (int off = 1; off < 32; off <<= 1) {
        int n = __shfl_up_sync(0xFFFFFFFFu, v, off);
        if (lane >= off) v += n;
    }
    if (lane == 31) swarp2[wid] = v;
    __syncthreads();
    if (tid < 32) {
        int w = swarp2[tid];
        #pragma unroll
        for (int off = 1; off < 32; off <<= 1) {
            int n = __shfl_up_sync(0xFFFFFFFFu, w, off);
            if (lane >= off) w += n;
        }
        swarp2[tid] = w;
    }
    __syncthreads();
    int incl = v + (wid ? swarp2[wid - 1] : 0);
    int total = swarp2[31];

    if (flag) {
        int m = incl - 1;
        float conf = ord2f((u32)(mykey >> 32));
        u32 flat = ~(u32)mykey;
        int cls = (int)(flat / KTOP);
        float4 raw = d_raw2[b * KTOP + tid];
        float* o = out + ((size_t)b * KTOP + m) * 6;
        o[0] = raw.x; o[1] = raw.y; o[2] = raw.z; o[3] = raw.w;
        o[4] = (float)cls; o[5] = conf;
    }
    for (int m = total + tid; m < KTOP; m += 1024) {
        float* o = out + ((size_t)b * KTOP + m) * 6;
        #pragma unroll
        for (int q = 0; q < 6; ++q) o[q] = 0.f;
    }
}

// ---------------- launch ------------------------------------------------------
extern "C" void kernel_launch(void* const* d_in, const int* in_sizes, int n_in,
                              void* d_out, int out_size) {
    const float*  cls   = (const float*)d_in[0];
    const float4* boxes = (const float4*)d_in[1];
    float* out = (float*)d_out;

    k_transpose<<<dim3((NPTS + TI - 1) / TI, BATCH), 512>>>(cls);
    k_sel1<<<NROWS, 1024>>>(boxes);
    k_nms1<<<NROWS, 1024>>>();
    k_sel2<<<BATCH, 1024>>>(boxes);
    k_nms2<<<BATCH, 1024>>>(out);
}